// round 17
// baseline (speedup 1.0000x reference)
#include <cuda_runtime.h>
#include <cuda_bf16.h>
#include <cuda_fp16.h>
#include <cstdint>

constexpr int B = 4;
constexpr int S = 4096;
constexpr int D = 256;
constexpr int L = 8921;

constexpr int NST = 16;     // S/256 s-tiles in K1
constexpr int NLT = 70;     // ceil(L/128)
constexpr int LPAD = NLT * 128;   // 8960

// ---------------- device scratch ------------------------------------------
__device__ float g_pm[(size_t)B * L * NST];
__device__ float g_pz[(size_t)B * L * NST];
__device__ float g_sf[(size_t)B * L * NST];   // per-(row,tile) alpha scale

// chunk-contiguous, SW128-swizzled operand arrays
// gU1*: [lt][kc][16KB]   (128 rows x 128B)
// gX1*: [b][st][kc][32KB] (256 rows x 128B)
// gV1 : [b][sc][32KB]     (256 d-rows x 128B)
__device__ __align__(128) uint8_t gU1h[(size_t)NLT * 4 * 16384];
__device__ __align__(128) uint8_t gU1l[(size_t)NLT * 4 * 16384];
__device__ __align__(128) uint8_t gX1h[(size_t)B * NST * 4 * 32768];
__device__ __align__(128) uint8_t gX1l[(size_t)B * NST * 4 * 32768];
__device__ __align__(128) uint8_t gV1 [(size_t)B * 64 * 32768];

// ---------------- helpers --------------------------------------------------
__device__ __forceinline__ uint32_t smem_u32(const void* p) {
    uint32_t a;
    asm("{ .reg .u64 t; cvta.to.shared.u64 t, %1; cvt.u32.u64 %0, t; }" : "=r"(a) : "l"(p));
    return a;
}
__device__ __forceinline__ void bulk_cp(uint32_t dst, const void* src, uint32_t bytes, uint32_t mb) {
    asm volatile("cp.async.bulk.shared::cluster.global.mbarrier::complete_tx::bytes "
                 "[%0], [%1], %2, [%3];"
                 :: "r"(dst), "l"(src), "r"(bytes), "r"(mb) : "memory");
}
__device__ __forceinline__ void mbar_init(uint32_t a, uint32_t n) {
    asm volatile("mbarrier.init.shared.b64 [%0], %1;" :: "r"(a), "r"(n) : "memory");
}
__device__ __forceinline__ void mbar_arrive_tx(uint32_t a, uint32_t bytes) {
    asm volatile("mbarrier.arrive.expect_tx.shared.b64 _, [%0], %1;"
                 :: "r"(a), "r"(bytes) : "memory");
}
__device__ __forceinline__ void mbar_wait(uint32_t a, uint32_t parity) {
    asm volatile(
        "{\n\t.reg .pred P;\n\t"
        "WL%=:\n\t"
        "mbarrier.try_wait.parity.acquire.cta.shared::cta.b64 P, [%0], %1, 0x989680;\n\t"
        "@P bra WD%=;\n\t"
        "bra WL%=;\n\t"
        "WD%=:\n\t}"
        :: "r"(a), "r"(parity) : "memory");
}
__device__ __forceinline__ void ldsm4(uint32_t* r, uint32_t a) {
    asm volatile("ldmatrix.sync.aligned.m8n8.x4.shared.b16 {%0,%1,%2,%3}, [%4];"
                 : "=r"(r[0]), "=r"(r[1]), "=r"(r[2]), "=r"(r[3]) : "r"(a));
}
__device__ __forceinline__ void mma_bf16(float* d, const uint32_t* a, uint32_t b0, uint32_t b1) {
    asm volatile("mma.sync.aligned.m16n8k16.row.col.f32.bf16.bf16.f32 "
                 "{%0,%1,%2,%3}, {%4,%5,%6,%7}, {%8,%9}, {%0,%1,%2,%3};"
                 : "+f"(d[0]), "+f"(d[1]), "+f"(d[2]), "+f"(d[3])
                 : "r"(a[0]), "r"(a[1]), "r"(a[2]), "r"(a[3]), "r"(b0), "r"(b1));
}
__device__ __forceinline__ void mma_f16(float* d, const uint32_t* a, uint32_t b0, uint32_t b1) {
    asm volatile("mma.sync.aligned.m16n8k16.row.col.f32.f16.f16.f32 "
                 "{%0,%1,%2,%3}, {%4,%5,%6,%7}, {%8,%9}, {%0,%1,%2,%3};"
                 : "+f"(d[0]), "+f"(d[1]), "+f"(d[2]), "+f"(d[3])
                 : "r"(a[0]), "r"(a[1]), "r"(a[2]), "r"(a[3]), "r"(b0), "r"(b1));
}
__device__ __forceinline__ float ex2f(float x) {
    float y;
    asm("ex2.approx.f32 %0, %1;" : "=f"(y) : "f"(x));
    return y;
}
__device__ __forceinline__ void split1(float v, __nv_bfloat16& h, __nv_bfloat16& l) {
    h = __float2bfloat16(v);
    l = __float2bfloat16(v - __bfloat162float(h));
}
__device__ __forceinline__ uint32_t pack2(__nv_bfloat16 a, __nv_bfloat16 b) {
    __nv_bfloat162 t = __halves2bfloat162(a, b);
    return *reinterpret_cast<uint32_t*>(&t);
}
__device__ __forceinline__ uint32_t packh2(float a, float b) {
    __half2 t = __floats2half2_rn(a, b);
    return *reinterpret_cast<uint32_t*>(&t);
}
// SW128 blocked-atom address: row r (8-row atoms of 128B rows), col byte within row
__device__ __forceinline__ uint32_t swadr(int r, int colb) {
    return (uint32_t)((r >> 3) * 1024 + (r & 7) * 128 + (colb ^ ((r & 7) << 4)));
}

// ---------------- smem layouts ----------------------------------------------
// K1: k-chunk 64; stage = Ah 16K | Al 16K | Bh 32K | Bl 32K
constexpr int OFF_AH = 0;
constexpr int OFF_AL = 16384;
constexpr int OFF_BH = 32768;
constexpr int OFF_BL = 65536;
constexpr int STAGE1 = 98304;
constexpr int STATS1 = 2 * STAGE1;           // 196608
constexpr int MB1    = STATS1 + 4864;        // 201472
constexpr int SMEM1  = 201728;

// K3: stage = A(alpha fp16) 16K | B(xT fp16 hi) 32K
constexpr int O3_A   = 0;
constexpr int O3_B   = 16384;
constexpr int STAGE3 = 49152;
constexpr int SFS3   = 2 * STAGE3;           // 98304
constexpr int MB3    = SFS3 + 8192;          // 106496
constexpr int SMEM3  = 106752;

constexpr int LDC = 264;   // K1 epilogue fp32 staging row stride

// ---------------- precompute kernels ---------------------------------------
__global__ void k_prep_u(const float* __restrict__ U) {
    int i = blockIdx.x * blockDim.x + threadIdx.x;       // over LPAD*64 float4s
    if (i >= LPAD * (D / 4)) return;
    int l = i >> 6;
    int q = i & 63;          // float4 index in row
    int k4 = q * 4;
    float4 v = (l < L) ? ((const float4*)U)[(size_t)l * 64 + q]
                       : make_float4(0.f, 0.f, 0.f, 0.f);
    const float LOG2E = 1.4426950408889634f;
    v.x *= LOG2E; v.y *= LOG2E; v.z *= LOG2E; v.w *= LOG2E;
    __nv_bfloat16 h0,h1,h2,h3,l0,l1,l2,l3;
    split1(v.x,h0,l0); split1(v.y,h1,l1); split1(v.z,h2,l2); split1(v.w,h3,l3);
    int lt = l >> 7, r = l & 127, c = k4 >> 6, kk = k4 & 63;
    size_t blk = ((size_t)lt * 4 + c) * 16384;
    uint32_t off = swadr(r, kk * 2);
    *(uint2*)(gU1h + blk + off) = make_uint2(pack2(h0,h1), pack2(h2,h3));
    *(uint2*)(gU1l + blk + off) = make_uint2(pack2(l0,l1), pack2(l2,l3));
}
// one pass over x: swizzled bf16 split (K1 B) + swizzled fp16 hi transposed (K3 B)
__global__ void k_prep_x(const float* __restrict__ x) {
    __shared__ float t[32][33];
    int b = blockIdx.z, s0 = blockIdx.x * 32, d0 = blockIdx.y * 32;
    int tx = threadIdx.x, ty = threadIdx.y;
    const float* xb = x + (size_t)b * S * D;
#pragma unroll
    for (int i = 0; i < 32; i += 8) {
        int s = s0 + ty + i;
        float v = xb[(size_t)s * D + d0 + tx];
        t[ty + i][tx] = v;
        __nv_bfloat16 h, l; split1(v, h, l);
        int st = s >> 8, r = s & 255, k = d0 + tx;
        int c = k >> 6, kk = k & 63;
        size_t blk = (((size_t)b * NST + st) * 4 + c) * 32768;
        uint32_t off = swadr(r, kk * 2);
        *(__nv_bfloat16*)(gX1h + blk + off) = h;
        *(__nv_bfloat16*)(gX1l + blk + off) = l;
    }
    __syncthreads();
#pragma unroll
    for (int i = 0; i < 32; i += 8) {
        int dr = d0 + ty + i;
        int s = s0 + tx;
        float v = t[tx][ty + i];
        int sc = s >> 6, ss = s & 63;
        size_t blk = ((size_t)b * 64 + sc) * 32768;
        uint32_t off = swadr(dr, ss * 2);
        *(__half*)(gV1 + blk + off) = __float2half(v);
    }
}

// ---------------- K1: e-values + per-tile stats -----------------------------
__global__ void __launch_bounds__(512) k1(float* __restrict__ ev)
{
    extern __shared__ __align__(128) char smem[];
    const uint32_t sb = smem_u32(smem);
    const int tid = threadIdx.x, lane = tid & 31, warp = tid >> 5;
    const int wm = warp & 3, wn = warp >> 2;
    const int bb = blockIdx.z, lt = blockIdx.y, st = blockIdx.x;
    const int l0 = lt * 128, s0 = st * 256;

    // lane address pieces
    const int ar0 = wm * 32 + (lane & 15);
    const int acx = (lane >> 4) * 16;
    const int br0 = wn * 64 + (lane & 7) + ((lane >> 4) & 1) * 8;
    const int bcx = ((lane >> 3) & 1) * 16;

    if (tid == 0) { mbar_init(sb + MB1, 1); mbar_init(sb + MB1 + 8, 1); }
    __syncthreads();

    float acc[2][8][4];
#pragma unroll
    for (int i = 0; i < 2; i++)
#pragma unroll
        for (int j = 0; j < 8; j++)
#pragma unroll
            for (int k = 0; k < 4; k++) acc[i][j][k] = 0.f;

    auto issue = [&](int c) {
        if (tid == 0) {
            uint32_t mb   = sb + MB1 + (c & 1) * 8;
            uint32_t base = sb + (c & 1) * STAGE1;
            mbar_arrive_tx(mb, 98304);
            size_t ablk = ((size_t)lt * 4 + c) * 16384;
            size_t bblk = (((size_t)bb * NST + st) * 4 + c) * 32768;
            bulk_cp(base + OFF_AH, gU1h + ablk, 16384, mb);
            bulk_cp(base + OFF_AL, gU1l + ablk, 16384, mb);
            bulk_cp(base + OFF_BH, gX1h + bblk, 32768, mb);
            bulk_cp(base + OFF_BL, gX1l + bblk, 32768, mb);
        }
    };

    issue(0);
    issue(1);

    for (int c = 0; c < 4; c++) {
        mbar_wait(sb + MB1 + (c & 1) * 8, (c >> 1) & 1);
        uint32_t base = sb + (c & 1) * STAGE1;
        // k64 chunk: 4 k16 steps, 3-term bf16, term-outermost
#pragma unroll
        for (int ks = 0; ks < 4; ks++) {
            uint32_t Ah[2][4], Al[2][4];
#pragma unroll
            for (int mt = 0; mt < 2; mt++) {
                uint32_t ao = swadr(ar0 + mt * 16, acx + ks * 32);
                ldsm4(Ah[mt], base + OFF_AH + ao);
                ldsm4(Al[mt], base + OFF_AL + ao);
            }
#pragma unroll
            for (int nph = 0; nph < 2; nph++) {
                uint32_t Bh[2][4], Bl[2][4];
#pragma unroll
                for (int j = 0; j < 2; j++) {
                    int np = nph * 2 + j;
                    uint32_t bo = swadr(br0 + np * 16, bcx + ks * 32);
                    ldsm4(Bh[j], base + OFF_BH + bo);
                    ldsm4(Bl[j], base + OFF_BL + bo);
                }
#pragma unroll
                for (int j = 0; j < 2; j++) {
                    int np = nph * 2 + j;
#pragma unroll
                    for (int mt = 0; mt < 2; mt++) {
                        mma_bf16(acc[mt][np*2],   Ah[mt], Bh[j][0], Bh[j][1]);
                        mma_bf16(acc[mt][np*2+1], Ah[mt], Bh[j][2], Bh[j][3]);
                    }
                }
#pragma unroll
                for (int j = 0; j < 2; j++) {
                    int np = nph * 2 + j;
#pragma unroll
                    for (int mt = 0; mt < 2; mt++) {
                        mma_bf16(acc[mt][np*2],   Ah[mt], Bl[j][0], Bl[j][1]);
                        mma_bf16(acc[mt][np*2+1], Ah[mt], Bl[j][2], Bl[j][3]);
                    }
                }
#pragma unroll
                for (int j = 0; j < 2; j++) {
                    int np = nph * 2 + j;
#pragma unroll
                    for (int mt = 0; mt < 2; mt++) {
                        mma_bf16(acc[mt][np*2],   Al[mt], Bh[j][0], Bh[j][1]);
                        mma_bf16(acc[mt][np*2+1], Al[mt], Bh[j][2], Bh[j][3]);
                    }
                }
            }
        }
        __syncthreads();
        if (c + 2 < 4) issue(c + 2);
    }

    // ---- epilogue (log2 domain): tile max, e-values, z ----
    float* spmax = (float*)(smem + STATS1);   // [4][128]
    float* spz   = spmax + 512;               // [4][128]
    float* srow  = spz + 512;                 // [128]
    float* Cs    = (float*)smem;              // [128][LDC] reuses stage area
    const int rbase = wm * 32 + (lane >> 2);

#pragma unroll
    for (int mt = 0; mt < 2; mt++)
#pragma unroll
        for (int h = 0; h < 2; h++) {
            float m = -3.4e38f;
#pragma unroll
            for (int nt = 0; nt < 8; nt++)
                m = fmaxf(m, fmaxf(acc[mt][nt][h*2], acc[mt][nt][h*2+1]));
            m = fmaxf(m, __shfl_xor_sync(0xffffffffu, m, 1));
            m = fmaxf(m, __shfl_xor_sync(0xffffffffu, m, 2));
            if ((lane & 3) == 0)
                spmax[wn * 128 + rbase + mt * 16 + h * 8] = m;
        }
    __syncthreads();
    if (tid < 128) {
        float m = fmaxf(fmaxf(spmax[tid], spmax[128 + tid]),
                        fmaxf(spmax[256 + tid], spmax[384 + tid]));
        srow[tid] = m;
    }
    __syncthreads();
#pragma unroll
    for (int mt = 0; mt < 2; mt++) {
        const int r = wm * 32 + mt * 16 + (lane >> 2);
        const int ccol = wn * 64 + (lane & 3) * 2;
#pragma unroll
        for (int h = 0; h < 2; h++) {
            float M = srow[rbase + mt * 16 + h * 8];
            float z = 0.f;
            float e0[8], e1[8];
#pragma unroll
            for (int nt = 0; nt < 8; nt++) {
                e0[nt] = ex2f(acc[mt][nt][h*2]     - M);
                e1[nt] = ex2f(acc[mt][nt][h*2 + 1] - M);
                z += e0[nt] + e1[nt];
            }
            z += __shfl_xor_sync(0xffffffffu, z, 1);
            z += __shfl_xor_sync(0xffffffffu, z, 2);
            if ((lane & 3) == 0)
                spz[wn * 128 + rbase + mt * 16 + h * 8] = z;
#pragma unroll
            for (int nt = 0; nt < 8; nt++)
                *(float2*)&Cs[(size_t)(r + h * 8) * LDC + ccol + nt * 8] =
                    make_float2(e0[nt], e1[nt]);
        }
    }
    __syncthreads();
    if (tid < 128) {
        int l = l0 + tid;
        if (l < L) {
            size_t p = ((size_t)bb * L + l) * NST + st;
            g_pm[p] = srow[tid];
            g_pz[p] = spz[tid] + spz[128 + tid] + spz[256 + tid] + spz[384 + tid];
        }
    }
#pragma unroll
    for (int t = 0; t < 16; t++) {
        int idx = t * 512 + tid;
        int row = idx >> 6, c4 = idx & 63;
        int l = l0 + row;
        if (l < L)
            *(float4*)(ev + ((size_t)bb * L + l) * S + s0 + c4 * 4) =
                *(const float4*)&Cs[(size_t)row * LDC + c4 * 4];
    }
}

// ---------------- K2: reduce stats -> per-tile alpha scales -----------------
__global__ void k_reduce() {
    int idx = blockIdx.x * blockDim.x + threadIdx.x;
    if (idx >= B * L) return;
    const float* pm = g_pm + (size_t)idx * NST;
    const float* pz = g_pz + (size_t)idx * NST;
    float M = -3.4e38f;
#pragma unroll
    for (int t = 0; t < NST; t++) M = fmaxf(M, pm[t]);
    float Z = 0.f;
#pragma unroll
    for (int t = 0; t < NST; t++) Z += pz[t] * ex2f(pm[t] - M);
    float Zi = 1.0f / Z;
#pragma unroll
    for (int t = 0; t < NST; t++)
        g_sf[(size_t)idx * NST + t] = ex2f(pm[t] - M) * Zi;
}

// ---------------- K3: alpha = e*sf + out = alpha_h @ x_h --------------------
__global__ void __launch_bounds__(512) k3(float* __restrict__ alpha,
                                          float* __restrict__ out)
{
    extern __shared__ __align__(128) char smem[];
    const uint32_t sb = smem_u32(smem);
    const int tid = threadIdx.x, lane = tid & 31, warp = tid >> 5;
    const int wm = warp & 3, wn = warp >> 2;
    const int bb = blockIdx.y, lt = blockIdx.x, l0 = lt * 128;

    const int ar0 = wm * 32 + (lane & 15);
    const int acx = (lane >> 4) * 16;
    const int br0 = wn * 64 + (lane & 7) + ((lane >> 4) & 1) * 8;
    const int bcx = ((lane >> 3) & 1) * 16;

    float* sfs = (float*)(smem + SFS3);   // [128][16]
#pragma unroll
    for (int t = 0; t < 4; t++) {
        int idx = t * 512 + tid;
        int r = idx >> 4, tt = idx & 15;
        int l = l0 + r;
        sfs[idx] = (l < L) ? g_sf[((size_t)bb * L + l) * NST + tt] : 0.f;
    }
    if (tid == 0) { mbar_init(sb + MB3, 1); mbar_init(sb + MB3 + 8, 1); }
    __syncthreads();

    float acc[2][8][4];
#pragma unroll
    for (int i = 0; i < 2; i++)
#pragma unroll
        for (int j = 0; j < 8; j++)
#pragma unroll
            for (int k = 0; k < 4; k++) acc[i][j][k] = 0.f;

    auto issue_b = [&](int c) {
        if (tid == 0) {
            uint32_t mb   = sb + MB3 + (c & 1) * 8;
            uint32_t base = sb + (c & 1) * STAGE3;
            mbar_arrive_tx(mb, 32768);
            bulk_cp(base + O3_B, gV1 + ((size_t)bb * 64 + c) * 32768, 32768, mb);
        }
    };
    auto a_load = [&](int c, float4* v) {
        int s0 = c * 64;
#pragma unroll
        for (int t = 0; t < 4; t++) {
            int idx = t * 512 + tid;
            int r = idx >> 4, c4 = idx & 15;
            int l = l0 + r;
            v[t] = (l < L)
                 ? *(const float4*)(alpha + ((size_t)bb * L + l) * S + s0 + c4 * 4)
                 : make_float4(0,0,0,0);
        }
    };
    auto a_store = [&](int c, const float4* v) {
        int s0 = c * 64;
        uint32_t base = (uint32_t)((c & 1) * STAGE3);
        const int tile = c >> 2;   // (c*64)/256
#pragma unroll
        for (int t = 0; t < 4; t++) {
            int idx = t * 512 + tid;
            int r = idx >> 4, c4 = idx & 15;
            int l = l0 + r;
            float4 a = v[t];
            float sf = sfs[r * 16 + tile];
            a.x *= sf; a.y *= sf; a.z *= sf; a.w *= sf;
            if (l >= L) a = make_float4(0,0,0,0);
            else
                *(float4*)(alpha + ((size_t)bb * L + l) * S + s0 + c4 * 4) = a;
            *(uint2*)(smem + base + O3_A + swadr(r, c4 * 8)) =
                make_uint2(packh2(a.x, a.y), packh2(a.z, a.w));
        }
    };

    {
        float4 v[4];
        issue_b(0); a_load(0, v); a_store(0, v);
        issue_b(1); a_load(1, v); a_store(1, v);
    }
    __syncthreads();

    constexpr int NC = 64;
    float4 vp[4];
    for (int c = 0; c < NC; c++) {
        bool pf = (c + 2 < NC);
        if (pf) a_load(c + 2, vp);
        mbar_wait(sb + MB3 + (c & 1) * 8, (c >> 1) & 1);
        uint32_t base = sb + (c & 1) * STAGE3;
#pragma unroll
        for (int ks = 0; ks < 4; ks++) {
            uint32_t Ah[2][4];
#pragma unroll
            for (int mt = 0; mt < 2; mt++)
                ldsm4(Ah[mt], base + O3_A + swadr(ar0 + mt * 16, acx + ks * 32));
#pragma unroll
            for (int np = 0; np < 4; np++) {
                uint32_t Bh[4];
                ldsm4(Bh, base + O3_B + swadr(br0 + np * 16, bcx + ks * 32));
#pragma unroll
                for (int mt = 0; mt < 2; mt++) {
                    mma_f16(acc[mt][np*2],   Ah[mt], Bh[0], Bh[1]);
                    mma_f16(acc[mt][np*2+1], Ah[mt], Bh[2], Bh[3]);
                }
            }
        }
        __syncthreads();
        if (pf) { issue_b(c + 2); a_store(c + 2, vp); }
        if (pf) __syncthreads();
    }

    // ---- epilogue: scatter out stores (measured cost-neutral) ----
#pragma unroll
    for (int mt = 0; mt < 2; mt++) {
        int r0 = l0 + wm * 32 + mt * 16 + (lane >> 2);
#pragma unroll
        for (int nt = 0; nt < 8; nt++) {
            int col = wn * 64 + nt * 8 + (lane & 3) * 2;
            if (r0 < L)
                *(float2*)(out + ((size_t)bb * L + r0) * D + col) =
                    make_float2(acc[mt][nt][0], acc[mt][nt][1]);
            if (r0 + 8 < L)
                *(float2*)(out + ((size_t)bb * L + r0 + 8) * D + col) =
                    make_float2(acc[mt][nt][2], acc[mt][nt][3]);
        }
    }
}

// ---------------------------------------------------------------------------
extern "C" void kernel_launch(void* const* d_in, const int* in_sizes, int n_in,
                              void* d_out, int out_size)
{
    const float* x = (const float*)d_in[0];   // [B,S,D]
    const float* U = (const float*)d_in[1];   // [L,D]

    float* out_ptr   = (float*)d_out;                      // [B,L,D]
    float* alpha_ptr = (float*)d_out + (size_t)B * L * D;  // [B,L,S]

    cudaFuncSetAttribute(k1, cudaFuncAttributeMaxDynamicSharedMemorySize, SMEM1);
    cudaFuncSetAttribute(k3, cudaFuncAttributeMaxDynamicSharedMemorySize, SMEM3);

    k_prep_u<<<(LPAD * (D / 4) + 255) / 256, 256>>>(U);
    k_prep_x<<<dim3(S / 32, D / 32, B), dim3(32, 8)>>>(x);

    k1<<<dim3(NST, NLT, B), 512, SMEM1>>>(alpha_ptr);   // writes e-values

    k_reduce<<<(B * L + 255) / 256, 256>>>();

    k3<<<dim3(NLT, B), 512, SMEM3>>>(alpha_ptr, out_ptr);
}